// round 13
// baseline (speedup 1.0000x reference)
#include <cuda_runtime.h>
#include <cuda_fp16.h>
#include <math.h>
#include <stdint.h>

#define T_TOK 4096
#define H_DIM 1024
#define I_DIM 2048
#define E_NUM 8
#define K_TOP 2
#define MAXP (T_TOK * K_TOP)

#define BM 128
#define BN 128
#define BK 32                      /* halves per k-stage */
#define AROW_B 80                  /* A smem row stride bytes */
#define BROW_B 272                 /* B smem row stride bytes */
#define ABYTES (BM * AROW_B)       /* 10240 */
#define BBYTES (BK * BROW_B)       /* 8704  */
#define STG    (ABYTES + BBYTES)   /* 18944 */
#define NST 4
#define SMEM_SZ (NST * STG)        /* 75776 */

#define GRID_Y 12                  /* 1536 rows/expert coverage */

// ---- static device scratch ----
__device__ int    g_count[E_NUM];
__device__ int    g_offset[E_NUM];
__device__ int    g_tok [E_NUM * MAXP];
__device__ float  g_gate[E_NUM * MAXP];
__device__ __half g_xh[(size_t)T_TOK * H_DIM];              // token-major fp16 x
__device__ __half g_h [(size_t)MAXP * I_DIM];               // gelu(fc), compacted rows
__device__ __half g_wfc_h  [(size_t)E_NUM * H_DIM * I_DIM];
__device__ __half g_wproj_h[(size_t)E_NUM * I_DIM * H_DIM];

// ================= helpers =================
__device__ __forceinline__ uint32_t smem_u32(const void* p) {
    uint32_t a;
    asm("{ .reg .u64 t; cvta.to.shared.u64 t, %1; cvt.u32.u64 %0, t; }" : "=r"(a) : "l"(p));
    return a;
}
__device__ __forceinline__ float gelu_exact(float v) {
    return 0.5f * v * (1.0f + erff(v * 0.7071067811865476f));
}
__device__ __forceinline__ void cp16(uint32_t dst, const void* src) {
    asm volatile("cp.async.ca.shared.global [%0], [%1], 16;" :: "r"(dst), "l"(src) : "memory");
}
__device__ __forceinline__ void cp_commit() {
    asm volatile("cp.async.commit_group;" ::: "memory");
}
__device__ __forceinline__ void cp_wait2() {
    asm volatile("cp.async.wait_group 2;" ::: "memory");
}
__device__ __forceinline__ void ldsm_x4(unsigned* r, uint32_t addr) {
    asm volatile("ldmatrix.sync.aligned.m8n8.x4.shared.b16 {%0,%1,%2,%3}, [%4];"
                 : "=r"(r[0]), "=r"(r[1]), "=r"(r[2]), "=r"(r[3]) : "r"(addr));
}
__device__ __forceinline__ void ldsm_x4_t(unsigned* r, uint32_t addr) {
    asm volatile("ldmatrix.sync.aligned.m8n8.x4.trans.shared.b16 {%0,%1,%2,%3}, [%4];"
                 : "=r"(r[0]), "=r"(r[1]), "=r"(r[2]), "=r"(r[3]) : "r"(addr));
}
__device__ __forceinline__ void mma_f16(float* d, const unsigned* a, const unsigned* b) {
    asm volatile(
        "mma.sync.aligned.m16n8k16.row.col.f32.f16.f16.f32 "
        "{%0,%1,%2,%3},{%4,%5,%6,%7},{%8,%9},{%0,%1,%2,%3};"
        : "+f"(d[0]), "+f"(d[1]), "+f"(d[2]), "+f"(d[3])
        : "r"(a[0]), "r"(a[1]), "r"(a[2]), "r"(a[3]),
          "r"(b[0]), "r"(b[1]));
}

// ================= routing: 8 blocks, one expert each =================
// Pass 1: every block counts all experts (register-local, shared reduce).
// Pass 2: block e scatters its own expert's (token, gate) pairs.
__global__ void route_kernel(const float* __restrict__ rw,
                             const int*   __restrict__ sel) {
    const int e   = blockIdx.x;
    const int tid = threadIdx.x;
    __shared__ int scnt[E_NUM];
    __shared__ int myslot;
    if (tid < E_NUM) scnt[tid] = 0;
    if (tid == 0) myslot = 0;
    __syncthreads();

    int loc[E_NUM];
#pragma unroll
    for (int i = 0; i < E_NUM; i++) loc[i] = 0;
    for (int p = tid; p < T_TOK * K_TOP; p += blockDim.x) {
        int s = sel[p];
#pragma unroll
        for (int i = 0; i < E_NUM; i++) loc[i] += (s == i);
    }
#pragma unroll
    for (int i = 0; i < E_NUM; i++)
        if (loc[i]) atomicAdd(&scnt[i], loc[i]);
    __syncthreads();

    if (tid == 0) {
        int off = 0;
#pragma unroll
        for (int i = 0; i < e; i++) off += scnt[i];
        g_count[e]  = scnt[e];
        g_offset[e] = off;
    }

    for (int p = tid; p < T_TOK * K_TOP; p += blockDim.x) {
        if (sel[p] == e) {
            int slot = atomicAdd(&myslot, 1);
            g_tok [e * MAXP + slot] = p / K_TOP;
            g_gate[e * MAXP + slot] = rw[p];
        }
    }
}

// ================= x -> fp16 (token-major, no routing dep) =============
__global__ void convert_x_kernel(const float* __restrict__ x) {
    int i = blockIdx.x * blockDim.x + threadIdx.x;   // float4 index
    float4 v = ((const float4*)x)[i];
    __half2 h0 = __floats2half2_rn(v.x, v.y);
    __half2 h1 = __floats2half2_rn(v.z, v.w);
    ((uint2*)g_xh)[i] = make_uint2(*(uint32_t*)&h0, *(uint32_t*)&h1);
}

// ================= weight convert -> fp16 (exact-cover grid) ===========
__global__ void convert_kernel(const float* __restrict__ src,
                               __half* __restrict__ dst) {
    int i = blockIdx.x * blockDim.x + threadIdx.x;
    float4 v = ((const float4*)src)[i];
    __half2 h0 = __floats2half2_rn(v.x, v.y);
    __half2 h1 = __floats2half2_rn(v.z, v.w);
    ((uint2*)dst)[i] = make_uint2(*(uint32_t*)&h0, *(uint32_t*)&h1);
}

// ================= grouped GEMM: 256 thr, 8 warps @ 64x32 (converged) ===
// IS_FC:  A rows gathered on the fly from token-major g_xh via g_tok.
// !IS_FC: A rows from compacted g_h.
template <bool IS_FC>
__global__ __launch_bounds__(256, 2)
void moe_gemm(const __half* __restrict__ wsrc, float* __restrict__ out) {
    const int e    = blockIdx.z;
    const int cnt  = g_count[e];
    const int row0 = blockIdx.y * BM;
    if (row0 >= cnt) return;
    const int col0 = blockIdx.x * BN;
    const int off  = g_offset[e];
    const int KDIM = IS_FC ? H_DIM : I_DIM;
    const int NDIM = IS_FC ? I_DIM : H_DIM;
    const int NKB  = KDIM / BK;

    extern __shared__ char sm[];
    const uint32_t smb = smem_u32(sm);

    const int tid  = threadIdx.x;
    const int warp = tid >> 5;
    const int lane = tid & 31;

    // ---- staging maps ----
    const int arow = tid >> 1;
    const int ahc  = (tid & 1) * 16;
    int ga = row0 + arow; if (ga >= cnt) ga = cnt - 1;
    const __half* aSrc;
    if (IS_FC) {
        const int tok = g_tok[e * MAXP + ga];       // on-the-fly gather
        aSrc = g_xh + (size_t)tok * H_DIM + ahc;
    } else {
        aSrc = g_h + (size_t)(off + ga) * KDIM + ahc;
    }
    const int brow = tid >> 3;
    const int bhc  = (tid & 7) * 16;
    const __half* bSrc = wsrc + (size_t)e * H_DIM * I_DIM
                       + (size_t)brow * NDIM + col0 + bhc;

    uint32_t aDst[NST], bDst[NST];
#pragma unroll
    for (int s = 0; s < NST; s++) {
        aDst[s] = smb + s * STG + arow * AROW_B + ahc * 2;
        bDst[s] = smb + s * STG + ABYTES + brow * BROW_B + bhc * 2;
    }

#define ISSUE(kb_, st_) do { \
    const __half* as_ = aSrc + (kb_) * BK; \
    cp16(aDst[st_], as_); cp16(aDst[st_] + 16, as_ + 8); \
    const __half* bs_ = bSrc + (size_t)(kb_) * BK * NDIM; \
    cp16(bDst[st_], bs_); cp16(bDst[st_] + 16, bs_ + 8); \
    } while (0)

    const int wm = warp >> 2;
    const int wn = warp & 3;
    const int g  = lane >> 2;
    const int t  = lane & 3;

    const int lrow = lane & 15;
    const int lsel = lane >> 4;
    const uint32_t aLdBase = (wm * 64 + lrow) * AROW_B + lsel * 16;
    const uint32_t bLdBase = ABYTES + lrow * BROW_B + (wn * 32 + lsel * 8) * 2;

    float acc[4][4][4];
#pragma unroll
    for (int mt = 0; mt < 4; mt++)
#pragma unroll
        for (int nt = 0; nt < 4; nt++)
#pragma unroll
            for (int r = 0; r < 4; r++) acc[mt][nt][r] = 0.f;

    ISSUE(0, 0); cp_commit();
    ISSUE(1, 1); cp_commit();
    ISSUE(2, 2); cp_commit();

#pragma unroll 1
    for (int kb = 0; kb < NKB; kb++) {
        cp_wait2();
        __syncthreads();
        const int st = kb & 3;
        if (kb + 3 < NKB) ISSUE(kb + 3, (kb + 3) & 3);
        cp_commit();

        const uint32_t stb = smb + st * STG;
#pragma unroll
        for (int ks = 0; ks < 2; ks++) {
            const int k0 = ks * 16;
            unsigned afr[4][4], bfr[2][4];
#pragma unroll
            for (int h = 0; h < 2; h++)
                ldsm_x4_t(bfr[h], stb + bLdBase + k0 * BROW_B + h * 32);
#pragma unroll
            for (int mt = 0; mt < 4; mt++)
                ldsm_x4(afr[mt], stb + aLdBase + mt * 16 * AROW_B + k0 * 2);
#pragma unroll
            for (int mt = 0; mt < 4; mt++) {
#pragma unroll
                for (int nt = 0; nt < 4; nt++)
                    mma_f16(acc[mt][nt], afr[mt], &bfr[nt >> 1][(nt & 1) * 2]);
            }
        }
    }
#undef ISSUE

#pragma unroll
    for (int mt = 0; mt < 4; mt++) {
        const int l0 = wm * 64 + mt * 16 + g;
        const int l1 = l0 + 8;
        const int lr0 = row0 + l0;
        const int lr1 = row0 + l1;
#pragma unroll
        for (int nt = 0; nt < 4; nt++) {
            const int c = col0 + wn * 32 + nt * 8 + 2 * t;
            if (IS_FC) {
                if (lr0 < cnt) {
                    __half2 v = __floats2half2_rn(gelu_exact(acc[mt][nt][0]),
                                                  gelu_exact(acc[mt][nt][1]));
                    *(__half2*)(g_h + (size_t)(off + lr0) * I_DIM + c) = v;
                }
                if (lr1 < cnt) {
                    __half2 v = __floats2half2_rn(gelu_exact(acc[mt][nt][2]),
                                                  gelu_exact(acc[mt][nt][3]));
                    *(__half2*)(g_h + (size_t)(off + lr1) * I_DIM + c) = v;
                }
            } else {
                if (lr0 < cnt) {
                    const float gate = g_gate[e * MAXP + lr0];
                    float* dst = out + (size_t)g_tok[e * MAXP + lr0] * H_DIM + c;
                    atomicAdd(dst,     gate * acc[mt][nt][0]);
                    atomicAdd(dst + 1, gate * acc[mt][nt][1]);
                }
                if (lr1 < cnt) {
                    const float gate = g_gate[e * MAXP + lr1];
                    float* dst = out + (size_t)g_tok[e * MAXP + lr1] * H_DIM + c;
                    atomicAdd(dst,     gate * acc[mt][nt][2]);
                    atomicAdd(dst + 1, gate * acc[mt][nt][3]);
                }
            }
        }
    }
}

// ================= launch (fork/join, two big GEMMs) ====================
extern "C" void kernel_launch(void* const* d_in, const int* in_sizes, int n_in,
                              void* d_out, int out_size) {
    const float* x     = (const float*)d_in[0];
    const float* rw    = (const float*)d_in[1];
    const int*   sel   = (const int*)  d_in[2];
    const float* wfc   = (const float*)d_in[3];
    const float* wproj = (const float*)d_in[4];
    float* out = (float*)d_out;

    static bool inited = false;
    static cudaStream_t sA, sB;
    static cudaEvent_t ev0, evA, evB;
    if (!inited) {
        cudaStreamCreateWithFlags(&sA, cudaStreamNonBlocking);
        cudaStreamCreateWithFlags(&sB, cudaStreamNonBlocking);
        cudaEventCreateWithFlags(&ev0, cudaEventDisableTiming);
        cudaEventCreateWithFlags(&evA, cudaEventDisableTiming);
        cudaEventCreateWithFlags(&evB, cudaEventDisableTiming);
        cudaFuncSetAttribute(moe_gemm<true>,  cudaFuncAttributeMaxDynamicSharedMemorySize, SMEM_SZ);
        cudaFuncSetAttribute(moe_gemm<false>, cudaFuncAttributeMaxDynamicSharedMemorySize, SMEM_SZ);
        inited = true;
    }

    __half* wfcH;  cudaGetSymbolAddress((void**)&wfcH, g_wfc_h);
    __half* wprH;  cudaGetSymbolAddress((void**)&wprH, g_wproj_h);

    const int nblk = E_NUM * H_DIM * I_DIM / 4 / 256;   // exact cover

    // fork side streams off the main (capture) stream
    cudaEventRecord(ev0, 0);
    cudaStreamWaitEvent(sA, ev0, 0);
    cudaStreamWaitEvent(sB, ev0, 0);

    // sA: convert wfc (gates fc GEMM)
    convert_kernel<<<nblk, 256, 0, sA>>>(wfc, wfcH);
    cudaEventRecord(evA, sA);

    // sB: convert wproj + zero output (gates proj GEMM)
    convert_kernel<<<nblk, 256, 0, sB>>>(wproj, wprH);
    cudaMemsetAsync(out, 0, (size_t)T_TOK * H_DIM * sizeof(float), sB);
    cudaEventRecord(evB, sB);

    // main: convert x + routing (both gate fc GEMM)
    convert_x_kernel<<<T_TOK * H_DIM / 4 / 256, 256>>>(x);
    route_kernel<<<E_NUM, 256>>>(rw, sel);

    // join: fc needs wfcH + xh + routing tables
    cudaStreamWaitEvent(0, evA, 0);
    dim3 fc_grid(I_DIM / BN, GRID_Y, E_NUM);
    moe_gemm<true><<<fc_grid, 256, SMEM_SZ>>>(wfcH, out);

    cudaStreamWaitEvent(0, evB, 0);
    dim3 pj_grid(H_DIM / BN, GRID_Y, E_NUM);
    moe_gemm<false><<<pj_grid, 256, SMEM_SZ>>>(wprH, out);
}

// round 14
// speedup vs baseline: 1.0855x; 1.0855x over previous
#include <cuda_runtime.h>
#include <cuda_fp16.h>
#include <math.h>
#include <stdint.h>

#define T_TOK 4096
#define H_DIM 1024
#define I_DIM 2048
#define E_NUM 8
#define K_TOP 2
#define MAXP (T_TOK * K_TOP)

#define BM 128
#define BN 128
#define BK 32                      /* halves per k-stage */
#define AROW_B 80                  /* A smem row stride bytes */
#define BROW_B 272                 /* B smem row stride bytes */
#define ABYTES (BM * AROW_B)       /* 10240 */
#define BBYTES (BK * BROW_B)       /* 8704  */
#define STG    (ABYTES + BBYTES)   /* 18944 */
#define NST 4
#define SMEM_SZ (NST * STG)        /* 75776 */

#define GRID_Y 12                  /* 1536 rows/expert coverage */

// ---- static device scratch ----
__device__ int    g_count[E_NUM];
__device__ int    g_offset[E_NUM];
__device__ int    g_tok [E_NUM * MAXP];
__device__ float  g_gate[E_NUM * MAXP];
__device__ __half g_xh[(size_t)T_TOK * H_DIM];              // token-major fp16 x
__device__ __half g_h [(size_t)MAXP * I_DIM];               // gelu(fc), compacted rows
__device__ __half g_wfc_h  [(size_t)E_NUM * H_DIM * I_DIM];
__device__ __half g_wproj_h[(size_t)E_NUM * I_DIM * H_DIM];

// ================= helpers =================
__device__ __forceinline__ uint32_t smem_u32(const void* p) {
    uint32_t a;
    asm("{ .reg .u64 t; cvta.to.shared.u64 t, %1; cvt.u32.u64 %0, t; }" : "=r"(a) : "l"(p));
    return a;
}
__device__ __forceinline__ float gelu_exact(float v) {
    return 0.5f * v * (1.0f + erff(v * 0.7071067811865476f));
}
__device__ __forceinline__ void cp16(uint32_t dst, const void* src) {
    asm volatile("cp.async.ca.shared.global [%0], [%1], 16;" :: "r"(dst), "l"(src) : "memory");
}
__device__ __forceinline__ void cp_commit() {
    asm volatile("cp.async.commit_group;" ::: "memory");
}
__device__ __forceinline__ void cp_wait2() {
    asm volatile("cp.async.wait_group 2;" ::: "memory");
}
__device__ __forceinline__ void ldsm_x4(unsigned* r, uint32_t addr) {
    asm volatile("ldmatrix.sync.aligned.m8n8.x4.shared.b16 {%0,%1,%2,%3}, [%4];"
                 : "=r"(r[0]), "=r"(r[1]), "=r"(r[2]), "=r"(r[3]) : "r"(addr));
}
__device__ __forceinline__ void ldsm_x4_t(unsigned* r, uint32_t addr) {
    asm volatile("ldmatrix.sync.aligned.m8n8.x4.trans.shared.b16 {%0,%1,%2,%3}, [%4];"
                 : "=r"(r[0]), "=r"(r[1]), "=r"(r[2]), "=r"(r[3]) : "r"(addr));
}
__device__ __forceinline__ void mma_f16(float* d, const unsigned* a, const unsigned* b) {
    asm volatile(
        "mma.sync.aligned.m16n8k16.row.col.f32.f16.f16.f32 "
        "{%0,%1,%2,%3},{%4,%5,%6,%7},{%8,%9},{%0,%1,%2,%3};"
        : "+f"(d[0]), "+f"(d[1]), "+f"(d[2]), "+f"(d[3])
        : "r"(a[0]), "r"(a[1]), "r"(a[2]), "r"(a[3]),
          "r"(b[0]), "r"(b[1]));
}
__device__ __forceinline__ void red_add_v2(float* dst, float v0, float v1) {
    asm volatile("red.global.add.v2.f32 [%0], {%1, %2};"
                 :: "l"(dst), "f"(v0), "f"(v1) : "memory");
}

// ================= routing (R12 single-block form) =================
__global__ void route_kernel(const float* __restrict__ rw,
                             const int*   __restrict__ sel) {
    __shared__ int sc[E_NUM];
    int tid = threadIdx.x;
    if (tid < E_NUM) sc[tid] = 0;
    __syncthreads();
    for (int p = tid; p < T_TOK * K_TOP; p += blockDim.x) {
        int e = sel[p];
        int slot = atomicAdd(&sc[e], 1);
        g_tok [e * MAXP + slot] = p / K_TOP;
        g_gate[e * MAXP + slot] = rw[p];
    }
    __syncthreads();
    if (tid == 0) {
        int off = 0;
        for (int e = 0; e < E_NUM; e++) {
            g_count[e]  = sc[e];
            g_offset[e] = off;
            off += sc[e];
        }
    }
}

// ================= x -> fp16 (token-major, no routing dep) =============
__global__ void convert_x_kernel(const float* __restrict__ x) {
    int i = blockIdx.x * blockDim.x + threadIdx.x;   // float4 index
    float4 v = ((const float4*)x)[i];
    __half2 h0 = __floats2half2_rn(v.x, v.y);
    __half2 h1 = __floats2half2_rn(v.z, v.w);
    ((uint2*)g_xh)[i] = make_uint2(*(uint32_t*)&h0, *(uint32_t*)&h1);
}

// ================= weight convert -> fp16 (R12 grid-stride form) =======
__global__ void convert_kernel(const float* __restrict__ src,
                               __half* __restrict__ dst, int n4) {
    int i = blockIdx.x * blockDim.x + threadIdx.x;
    const int stride = gridDim.x * blockDim.x;
    for (; i < n4; i += stride) {
        float4 v = ((const float4*)src)[i];
        __half2 h0 = __floats2half2_rn(v.x, v.y);
        __half2 h1 = __floats2half2_rn(v.z, v.w);
        ((uint2*)dst)[i] = make_uint2(*(uint32_t*)&h0, *(uint32_t*)&h1);
    }
}

// ================= grouped GEMM: 256 thr, 8 warps @ 64x32 (converged) ===
// IS_FC:  A rows gathered on the fly from token-major g_xh via g_tok.
// !IS_FC: A rows from compacted g_h; scatter via red.global.add.v2.f32.
template <bool IS_FC>
__global__ __launch_bounds__(256, 2)
void moe_gemm(const __half* __restrict__ wsrc, float* __restrict__ out) {
    const int e    = blockIdx.z;
    const int cnt  = g_count[e];
    const int row0 = blockIdx.y * BM;
    if (row0 >= cnt) return;
    const int col0 = blockIdx.x * BN;
    const int off  = g_offset[e];
    const int KDIM = IS_FC ? H_DIM : I_DIM;
    const int NDIM = IS_FC ? I_DIM : H_DIM;
    const int NKB  = KDIM / BK;

    extern __shared__ char sm[];
    const uint32_t smb = smem_u32(sm);

    const int tid  = threadIdx.x;
    const int warp = tid >> 5;
    const int lane = tid & 31;

    // ---- staging maps ----
    const int arow = tid >> 1;
    const int ahc  = (tid & 1) * 16;
    int ga = row0 + arow; if (ga >= cnt) ga = cnt - 1;
    const __half* aSrc;
    if (IS_FC) {
        const int tok = g_tok[e * MAXP + ga];       // on-the-fly gather
        aSrc = g_xh + (size_t)tok * H_DIM + ahc;
    } else {
        aSrc = g_h + (size_t)(off + ga) * KDIM + ahc;
    }
    const int brow = tid >> 3;
    const int bhc  = (tid & 7) * 16;
    const __half* bSrc = wsrc + (size_t)e * H_DIM * I_DIM
                       + (size_t)brow * NDIM + col0 + bhc;

    uint32_t aDst[NST], bDst[NST];
#pragma unroll
    for (int s = 0; s < NST; s++) {
        aDst[s] = smb + s * STG + arow * AROW_B + ahc * 2;
        bDst[s] = smb + s * STG + ABYTES + brow * BROW_B + bhc * 2;
    }

#define ISSUE(kb_, st_) do { \
    const __half* as_ = aSrc + (kb_) * BK; \
    cp16(aDst[st_], as_); cp16(aDst[st_] + 16, as_ + 8); \
    const __half* bs_ = bSrc + (size_t)(kb_) * BK * NDIM; \
    cp16(bDst[st_], bs_); cp16(bDst[st_] + 16, bs_ + 8); \
    } while (0)

    const int wm = warp >> 2;
    const int wn = warp & 3;
    const int g  = lane >> 2;
    const int t  = lane & 3;

    const int lrow = lane & 15;
    const int lsel = lane >> 4;
    const uint32_t aLdBase = (wm * 64 + lrow) * AROW_B + lsel * 16;
    const uint32_t bLdBase = ABYTES + lrow * BROW_B + (wn * 32 + lsel * 8) * 2;

    float acc[4][4][4];
#pragma unroll
    for (int mt = 0; mt < 4; mt++)
#pragma unroll
        for (int nt = 0; nt < 4; nt++)
#pragma unroll
            for (int r = 0; r < 4; r++) acc[mt][nt][r] = 0.f;

    ISSUE(0, 0); cp_commit();
    ISSUE(1, 1); cp_commit();
    ISSUE(2, 2); cp_commit();

#pragma unroll 1
    for (int kb = 0; kb < NKB; kb++) {
        cp_wait2();
        __syncthreads();
        const int st = kb & 3;
        if (kb + 3 < NKB) ISSUE(kb + 3, (kb + 3) & 3);
        cp_commit();

        const uint32_t stb = smb + st * STG;
#pragma unroll
        for (int ks = 0; ks < 2; ks++) {
            const int k0 = ks * 16;
            unsigned afr[4][4], bfr[2][4];
#pragma unroll
            for (int h = 0; h < 2; h++)
                ldsm_x4_t(bfr[h], stb + bLdBase + k0 * BROW_B + h * 32);
#pragma unroll
            for (int mt = 0; mt < 4; mt++)
                ldsm_x4(afr[mt], stb + aLdBase + mt * 16 * AROW_B + k0 * 2);
#pragma unroll
            for (int mt = 0; mt < 4; mt++) {
#pragma unroll
                for (int nt = 0; nt < 4; nt++)
                    mma_f16(acc[mt][nt], afr[mt], &bfr[nt >> 1][(nt & 1) * 2]);
            }
        }
    }
#undef ISSUE

#pragma unroll
    for (int mt = 0; mt < 4; mt++) {
        const int l0 = wm * 64 + mt * 16 + g;
        const int l1 = l0 + 8;
        const int lr0 = row0 + l0;
        const int lr1 = row0 + l1;
#pragma unroll
        for (int nt = 0; nt < 4; nt++) {
            const int c = col0 + wn * 32 + nt * 8 + 2 * t;
            if (IS_FC) {
                if (lr0 < cnt) {
                    __half2 v = __floats2half2_rn(gelu_exact(acc[mt][nt][0]),
                                                  gelu_exact(acc[mt][nt][1]));
                    *(__half2*)(g_h + (size_t)(off + lr0) * I_DIM + c) = v;
                }
                if (lr1 < cnt) {
                    __half2 v = __floats2half2_rn(gelu_exact(acc[mt][nt][2]),
                                                  gelu_exact(acc[mt][nt][3]));
                    *(__half2*)(g_h + (size_t)(off + lr1) * I_DIM + c) = v;
                }
            } else {
                if (lr0 < cnt) {
                    const float gate = g_gate[e * MAXP + lr0];
                    float* dst = out + (size_t)g_tok[e * MAXP + lr0] * H_DIM + c;
                    red_add_v2(dst, gate * acc[mt][nt][0], gate * acc[mt][nt][1]);
                }
                if (lr1 < cnt) {
                    const float gate = g_gate[e * MAXP + lr1];
                    float* dst = out + (size_t)g_tok[e * MAXP + lr1] * H_DIM + c;
                    red_add_v2(dst, gate * acc[mt][nt][2], gate * acc[mt][nt][3]);
                }
            }
        }
    }
}

// ================= launch (fork/join, two big GEMMs) ====================
extern "C" void kernel_launch(void* const* d_in, const int* in_sizes, int n_in,
                              void* d_out, int out_size) {
    const float* x     = (const float*)d_in[0];
    const float* rw    = (const float*)d_in[1];
    const int*   sel   = (const int*)  d_in[2];
    const float* wfc   = (const float*)d_in[3];
    const float* wproj = (const float*)d_in[4];
    float* out = (float*)d_out;

    static bool inited = false;
    static cudaStream_t sA, sB;
    static cudaEvent_t ev0, evA, evB;
    if (!inited) {
        cudaStreamCreateWithFlags(&sA, cudaStreamNonBlocking);
        cudaStreamCreateWithFlags(&sB, cudaStreamNonBlocking);
        cudaEventCreateWithFlags(&ev0, cudaEventDisableTiming);
        cudaEventCreateWithFlags(&evA, cudaEventDisableTiming);
        cudaEventCreateWithFlags(&evB, cudaEventDisableTiming);
        cudaFuncSetAttribute(moe_gemm<true>,  cudaFuncAttributeMaxDynamicSharedMemorySize, SMEM_SZ);
        cudaFuncSetAttribute(moe_gemm<false>, cudaFuncAttributeMaxDynamicSharedMemorySize, SMEM_SZ);
        inited = true;
    }

    __half* wfcH;  cudaGetSymbolAddress((void**)&wfcH, g_wfc_h);
    __half* wprH;  cudaGetSymbolAddress((void**)&wprH, g_wproj_h);

    const int n4 = E_NUM * H_DIM * I_DIM / 4;

    // fork side streams off the main (capture) stream
    cudaEventRecord(ev0, 0);
    cudaStreamWaitEvent(sA, ev0, 0);
    cudaStreamWaitEvent(sB, ev0, 0);

    // sA: convert wfc (gates fc GEMM)
    convert_kernel<<<1184, 256, 0, sA>>>(wfc, wfcH, n4);
    cudaEventRecord(evA, sA);

    // sB: convert wproj + zero output (gates proj GEMM)
    convert_kernel<<<1184, 256, 0, sB>>>(wproj, wprH, n4);
    cudaMemsetAsync(out, 0, (size_t)T_TOK * H_DIM * sizeof(float), sB);
    cudaEventRecord(evB, sB);

    // main: convert x + routing (both gate fc GEMM)
    convert_x_kernel<<<T_TOK * H_DIM / 4 / 256, 256>>>(x);
    route_kernel<<<1, 512>>>(rw, sel);

    // join: fc needs wfcH + xh + routing tables
    cudaStreamWaitEvent(0, evA, 0);
    dim3 fc_grid(I_DIM / BN, GRID_Y, E_NUM);
    moe_gemm<true><<<fc_grid, 256, SMEM_SZ>>>(wfcH, out);

    cudaStreamWaitEvent(0, evB, 0);
    dim3 pj_grid(H_DIM / BN, GRID_Y, E_NUM);
    moe_gemm<false><<<pj_grid, 256, SMEM_SZ>>>(wprH, out);
}

// round 15
// speedup vs baseline: 1.1300x; 1.0410x over previous
#include <cuda_runtime.h>
#include <cuda_fp16.h>
#include <math.h>
#include <stdint.h>

#define T_TOK 4096
#define H_DIM 1024
#define I_DIM 2048
#define E_NUM 8
#define K_TOP 2
#define MAXP (T_TOK * K_TOP)

#define BM 128
#define BN 128
#define BK 32                      /* halves per k-stage */
#define AROW_B 80                  /* A smem row stride bytes */
#define BROW_B 272                 /* B smem row stride bytes */
#define ABYTES (BM * AROW_B)       /* 10240 */
#define BBYTES (BK * BROW_B)       /* 8704  */
#define STG    (ABYTES + BBYTES)   /* 18944 */
#define NST 4
#define SMEM_SZ (NST * STG)        /* 75776 */

#define GRID_Y 12                  /* 1536 rows/expert coverage */

// ---- static device scratch ----
__device__ int    g_count[E_NUM];
__device__ int    g_offset[E_NUM];
__device__ int    g_tok [E_NUM * MAXP];
__device__ float  g_gate[E_NUM * MAXP];
__device__ __half g_xh[(size_t)T_TOK * H_DIM];              // token-major fp16 x
__device__ __half g_h [(size_t)MAXP * I_DIM];               // gelu(fc), compacted rows
__device__ __half g_wfc_h  [(size_t)E_NUM * H_DIM * I_DIM];
__device__ __half g_wproj_h[(size_t)E_NUM * I_DIM * H_DIM];

// ================= helpers =================
__device__ __forceinline__ uint32_t smem_u32(const void* p) {
    uint32_t a;
    asm("{ .reg .u64 t; cvta.to.shared.u64 t, %1; cvt.u32.u64 %0, t; }" : "=r"(a) : "l"(p));
    return a;
}
__device__ __forceinline__ float gelu_exact(float v) {
    return 0.5f * v * (1.0f + erff(v * 0.7071067811865476f));
}
__device__ __forceinline__ void cp16(uint32_t dst, const void* src) {
    asm volatile("cp.async.ca.shared.global [%0], [%1], 16;" :: "r"(dst), "l"(src) : "memory");
}
__device__ __forceinline__ void cp_commit() {
    asm volatile("cp.async.commit_group;" ::: "memory");
}
__device__ __forceinline__ void cp_wait2() {
    asm volatile("cp.async.wait_group 2;" ::: "memory");
}
__device__ __forceinline__ void ldsm_x4(unsigned* r, uint32_t addr) {
    asm volatile("ldmatrix.sync.aligned.m8n8.x4.shared.b16 {%0,%1,%2,%3}, [%4];"
                 : "=r"(r[0]), "=r"(r[1]), "=r"(r[2]), "=r"(r[3]) : "r"(addr));
}
__device__ __forceinline__ void ldsm_x4_t(unsigned* r, uint32_t addr) {
    asm volatile("ldmatrix.sync.aligned.m8n8.x4.trans.shared.b16 {%0,%1,%2,%3}, [%4];"
                 : "=r"(r[0]), "=r"(r[1]), "=r"(r[2]), "=r"(r[3]) : "r"(addr));
}
__device__ __forceinline__ void mma_f16(float* d, const unsigned* a, const unsigned* b) {
    asm volatile(
        "mma.sync.aligned.m16n8k16.row.col.f32.f16.f16.f32 "
        "{%0,%1,%2,%3},{%4,%5,%6,%7},{%8,%9},{%0,%1,%2,%3};"
        : "+f"(d[0]), "+f"(d[1]), "+f"(d[2]), "+f"(d[3])
        : "r"(a[0]), "r"(a[1]), "r"(a[2]), "r"(a[3]),
          "r"(b[0]), "r"(b[1]));
}
__device__ __forceinline__ void red_add_v2(float* dst, float v0, float v1) {
    asm volatile("red.global.add.v2.f32 [%0], {%1, %2};"
                 :: "l"(dst), "f"(v0), "f"(v1) : "memory");
}

// ================= routing: per-token with duplicate-expert merge =======
// Reference semantics: gates[t,e] = sum of routing weights of picks hitting e.
// If both K=2 picks hit the same expert, emit ONE row with summed gate.
__global__ void route_kernel(const float* __restrict__ rw,
                             const int*   __restrict__ sel) {
    __shared__ int sc[E_NUM];
    int tid = threadIdx.x;
    if (tid < E_NUM) sc[tid] = 0;
    __syncthreads();
    for (int t = tid; t < T_TOK; t += blockDim.x) {
        int   e0 = sel[2 * t],     e1 = sel[2 * t + 1];
        float r0 = rw [2 * t],     r1 = rw [2 * t + 1];
        if (e0 == e1) {
            int slot = atomicAdd(&sc[e0], 1);
            g_tok [e0 * MAXP + slot] = t;
            g_gate[e0 * MAXP + slot] = r0 + r1;
        } else {
            int s0 = atomicAdd(&sc[e0], 1);
            g_tok [e0 * MAXP + s0] = t;
            g_gate[e0 * MAXP + s0] = r0;
            int s1 = atomicAdd(&sc[e1], 1);
            g_tok [e1 * MAXP + s1] = t;
            g_gate[e1 * MAXP + s1] = r1;
        }
    }
    __syncthreads();
    if (tid == 0) {
        int off = 0;
        for (int e = 0; e < E_NUM; e++) {
            g_count[e]  = sc[e];
            g_offset[e] = off;
            off += sc[e];
        }
    }
}

// ================= x -> fp16 (token-major, no routing dep) =============
__global__ void convert_x_kernel(const float* __restrict__ x) {
    int i = blockIdx.x * blockDim.x + threadIdx.x;   // float4 index
    float4 v = ((const float4*)x)[i];
    __half2 h0 = __floats2half2_rn(v.x, v.y);
    __half2 h1 = __floats2half2_rn(v.z, v.w);
    ((uint2*)g_xh)[i] = make_uint2(*(uint32_t*)&h0, *(uint32_t*)&h1);
}

// ================= weight convert -> fp16 =================
__global__ void convert_kernel(const float* __restrict__ src,
                               __half* __restrict__ dst, int n4) {
    int i = blockIdx.x * blockDim.x + threadIdx.x;
    const int stride = gridDim.x * blockDim.x;
    for (; i < n4; i += stride) {
        float4 v = ((const float4*)src)[i];
        __half2 h0 = __floats2half2_rn(v.x, v.y);
        __half2 h1 = __floats2half2_rn(v.z, v.w);
        ((uint2*)dst)[i] = make_uint2(*(uint32_t*)&h0, *(uint32_t*)&h1);
    }
}

// ================= grouped GEMM: 256 thr, 8 warps @ 64x32 (converged) ===
// IS_FC:  A rows gathered on the fly from token-major g_xh via g_tok.
// !IS_FC: A rows from compacted g_h; scatter via red.global.add.v2.f32.
template <bool IS_FC>
__global__ __launch_bounds__(256, 2)
void moe_gemm(const __half* __restrict__ wsrc, float* __restrict__ out) {
    const int e    = blockIdx.z;
    const int cnt  = g_count[e];
    const int row0 = blockIdx.y * BM;
    if (row0 >= cnt) return;
    const int col0 = blockIdx.x * BN;
    const int off  = g_offset[e];
    const int KDIM = IS_FC ? H_DIM : I_DIM;
    const int NDIM = IS_FC ? I_DIM : H_DIM;
    const int NKB  = KDIM / BK;

    extern __shared__ char sm[];
    const uint32_t smb = smem_u32(sm);

    const int tid  = threadIdx.x;
    const int warp = tid >> 5;
    const int lane = tid & 31;

    // ---- staging maps ----
    const int arow = tid >> 1;
    const int ahc  = (tid & 1) * 16;
    int ga = row0 + arow; if (ga >= cnt) ga = cnt - 1;
    const __half* aSrc;
    if (IS_FC) {
        const int tok = g_tok[e * MAXP + ga];       // on-the-fly gather
        aSrc = g_xh + (size_t)tok * H_DIM + ahc;
    } else {
        aSrc = g_h + (size_t)(off + ga) * KDIM + ahc;
    }
    const int brow = tid >> 3;
    const int bhc  = (tid & 7) * 16;
    const __half* bSrc = wsrc + (size_t)e * H_DIM * I_DIM
                       + (size_t)brow * NDIM + col0 + bhc;

    uint32_t aDst[NST], bDst[NST];
#pragma unroll
    for (int s = 0; s < NST; s++) {
        aDst[s] = smb + s * STG + arow * AROW_B + ahc * 2;
        bDst[s] = smb + s * STG + ABYTES + brow * BROW_B + bhc * 2;
    }

#define ISSUE(kb_, st_) do { \
    const __half* as_ = aSrc + (kb_) * BK; \
    cp16(aDst[st_], as_); cp16(aDst[st_] + 16, as_ + 8); \
    const __half* bs_ = bSrc + (size_t)(kb_) * BK * NDIM; \
    cp16(bDst[st_], bs_); cp16(bDst[st_] + 16, bs_ + 8); \
    } while (0)

    const int wm = warp >> 2;
    const int wn = warp & 3;
    const int g  = lane >> 2;
    const int t  = lane & 3;

    const int lrow = lane & 15;
    const int lsel = lane >> 4;
    const uint32_t aLdBase = (wm * 64 + lrow) * AROW_B + lsel * 16;
    const uint32_t bLdBase = ABYTES + lrow * BROW_B + (wn * 32 + lsel * 8) * 2;

    float acc[4][4][4];
#pragma unroll
    for (int mt = 0; mt < 4; mt++)
#pragma unroll
        for (int nt = 0; nt < 4; nt++)
#pragma unroll
            for (int r = 0; r < 4; r++) acc[mt][nt][r] = 0.f;

    ISSUE(0, 0); cp_commit();
    ISSUE(1, 1); cp_commit();
    ISSUE(2, 2); cp_commit();

#pragma unroll 1
    for (int kb = 0; kb < NKB; kb++) {
        cp_wait2();
        __syncthreads();
        const int st = kb & 3;
        if (kb + 3 < NKB) ISSUE(kb + 3, (kb + 3) & 3);
        cp_commit();

        const uint32_t stb = smb + st * STG;
#pragma unroll
        for (int ks = 0; ks < 2; ks++) {
            const int k0 = ks * 16;
            unsigned afr[4][4], bfr[2][4];
#pragma unroll
            for (int h = 0; h < 2; h++)
                ldsm_x4_t(bfr[h], stb + bLdBase + k0 * BROW_B + h * 32);
#pragma unroll
            for (int mt = 0; mt < 4; mt++)
                ldsm_x4(afr[mt], stb + aLdBase + mt * 16 * AROW_B + k0 * 2);
#pragma unroll
            for (int mt = 0; mt < 4; mt++) {
#pragma unroll
                for (int nt = 0; nt < 4; nt++)
                    mma_f16(acc[mt][nt], afr[mt], &bfr[nt >> 1][(nt & 1) * 2]);
            }
        }
    }
#undef ISSUE

#pragma unroll
    for (int mt = 0; mt < 4; mt++) {
        const int l0 = wm * 64 + mt * 16 + g;
        const int l1 = l0 + 8;
        const int lr0 = row0 + l0;
        const int lr1 = row0 + l1;
#pragma unroll
        for (int nt = 0; nt < 4; nt++) {
            const int c = col0 + wn * 32 + nt * 8 + 2 * t;
            if (IS_FC) {
                if (lr0 < cnt) {
                    __half2 v = __floats2half2_rn(gelu_exact(acc[mt][nt][0]),
                                                  gelu_exact(acc[mt][nt][1]));
                    *(__half2*)(g_h + (size_t)(off + lr0) * I_DIM + c) = v;
                }
                if (lr1 < cnt) {
                    __half2 v = __floats2half2_rn(gelu_exact(acc[mt][nt][2]),
                                                  gelu_exact(acc[mt][nt][3]));
                    *(__half2*)(g_h + (size_t)(off + lr1) * I_DIM + c) = v;
                }
            } else {
                if (lr0 < cnt) {
                    const float gate = g_gate[e * MAXP + lr0];
                    float* dst = out + (size_t)g_tok[e * MAXP + lr0] * H_DIM + c;
                    red_add_v2(dst, gate * acc[mt][nt][0], gate * acc[mt][nt][1]);
                }
                if (lr1 < cnt) {
                    const float gate = g_gate[e * MAXP + lr1];
                    float* dst = out + (size_t)g_tok[e * MAXP + lr1] * H_DIM + c;
                    red_add_v2(dst, gate * acc[mt][nt][2], gate * acc[mt][nt][3]);
                }
            }
        }
    }
}

// ================= launch (fork/join, two big GEMMs) ====================
extern "C" void kernel_launch(void* const* d_in, const int* in_sizes, int n_in,
                              void* d_out, int out_size) {
    const float* x     = (const float*)d_in[0];
    const float* rw    = (const float*)d_in[1];
    const int*   sel   = (const int*)  d_in[2];
    const float* wfc   = (const float*)d_in[3];
    const float* wproj = (const float*)d_in[4];
    float* out = (float*)d_out;

    static bool inited = false;
    static cudaStream_t sA, sB;
    static cudaEvent_t ev0, evA, evB;
    if (!inited) {
        cudaStreamCreateWithFlags(&sA, cudaStreamNonBlocking);
        cudaStreamCreateWithFlags(&sB, cudaStreamNonBlocking);
        cudaEventCreateWithFlags(&ev0, cudaEventDisableTiming);
        cudaEventCreateWithFlags(&evA, cudaEventDisableTiming);
        cudaEventCreateWithFlags(&evB, cudaEventDisableTiming);
        cudaFuncSetAttribute(moe_gemm<true>,  cudaFuncAttributeMaxDynamicSharedMemorySize, SMEM_SZ);
        cudaFuncSetAttribute(moe_gemm<false>, cudaFuncAttributeMaxDynamicSharedMemorySize, SMEM_SZ);
        inited = true;
    }

    __half* wfcH;  cudaGetSymbolAddress((void**)&wfcH, g_wfc_h);
    __half* wprH;  cudaGetSymbolAddress((void**)&wprH, g_wproj_h);

    const int n4 = E_NUM * H_DIM * I_DIM / 4;

    // fork side streams off the main (capture) stream
    cudaEventRecord(ev0, 0);
    cudaStreamWaitEvent(sA, ev0, 0);
    cudaStreamWaitEvent(sB, ev0, 0);

    // sA: convert wfc (gates fc GEMM)
    convert_kernel<<<1184, 256, 0, sA>>>(wfc, wfcH, n4);
    cudaEventRecord(evA, sA);

    // sB: convert wproj + zero output (gates proj GEMM)
    convert_kernel<<<1184, 256, 0, sB>>>(wproj, wprH, n4);
    cudaMemsetAsync(out, 0, (size_t)T_TOK * H_DIM * sizeof(float), sB);
    cudaEventRecord(evB, sB);

    // main: convert x + routing (both gate fc GEMM)
    convert_x_kernel<<<T_TOK * H_DIM / 4 / 256, 256>>>(x);
    route_kernel<<<1, 512>>>(rw, sel);

    // join: fc needs wfcH + xh + routing tables
    cudaStreamWaitEvent(0, evA, 0);
    dim3 fc_grid(I_DIM / BN, GRID_Y, E_NUM);
    moe_gemm<true><<<fc_grid, 256, SMEM_SZ>>>(wfcH, out);

    cudaStreamWaitEvent(0, evB, 0);
    dim3 pj_grid(H_DIM / BN, GRID_Y, E_NUM);
    moe_gemm<false><<<pj_grid, 256, SMEM_SZ>>>(wprH, out);
}

// round 16
// speedup vs baseline: 1.1301x; 1.0001x over previous
#include <cuda_runtime.h>
#include <cuda_fp16.h>
#include <math.h>
#include <stdint.h>

#define T_TOK 4096
#define H_DIM 1024
#define I_DIM 2048
#define E_NUM 8
#define K_TOP 2
#define MAXP (T_TOK * K_TOP)

#define BM 128
#define BN 128
#define BK 32                      /* halves per k-stage */
#define AROW_B 80                  /* A smem row stride bytes */
#define BROW_B 272                 /* B smem row stride bytes */
#define ABYTES (BM * AROW_B)       /* 10240 */
#define BBYTES (BK * BROW_B)       /* 8704  */
#define STG    (ABYTES + BBYTES)   /* 18944 */
#define NST 4
#define SMEM_SZ (NST * STG)        /* 75776 */

#define PERSIST_CTAS 304           /* 152 SMs x 2 CTAs */

// ---- static device scratch ----
__device__ int    g_ctr[2];        // persistent tile counters (fc, proj)
__device__ int    g_count[E_NUM];
__device__ int    g_offset[E_NUM];
__device__ int    g_tok [E_NUM * MAXP];
__device__ float  g_gate[E_NUM * MAXP];
__device__ __half g_xh[(size_t)T_TOK * H_DIM];              // token-major fp16 x
__device__ __half g_h [(size_t)MAXP * I_DIM];               // gelu(fc), compacted rows
__device__ __half g_wfc_h  [(size_t)E_NUM * H_DIM * I_DIM];
__device__ __half g_wproj_h[(size_t)E_NUM * I_DIM * H_DIM];

// ================= helpers =================
__device__ __forceinline__ uint32_t smem_u32(const void* p) {
    uint32_t a;
    asm("{ .reg .u64 t; cvta.to.shared.u64 t, %1; cvt.u32.u64 %0, t; }" : "=r"(a) : "l"(p));
    return a;
}
__device__ __forceinline__ float gelu_exact(float v) {
    return 0.5f * v * (1.0f + erff(v * 0.7071067811865476f));
}
__device__ __forceinline__ void cp16(uint32_t dst, const void* src) {
    asm volatile("cp.async.ca.shared.global [%0], [%1], 16;" :: "r"(dst), "l"(src) : "memory");
}
__device__ __forceinline__ void cp_commit() {
    asm volatile("cp.async.commit_group;" ::: "memory");
}
__device__ __forceinline__ void cp_wait2() {
    asm volatile("cp.async.wait_group 2;" ::: "memory");
}
__device__ __forceinline__ void ldsm_x4(unsigned* r, uint32_t addr) {
    asm volatile("ldmatrix.sync.aligned.m8n8.x4.shared.b16 {%0,%1,%2,%3}, [%4];"
                 : "=r"(r[0]), "=r"(r[1]), "=r"(r[2]), "=r"(r[3]) : "r"(addr));
}
__device__ __forceinline__ void ldsm_x4_t(unsigned* r, uint32_t addr) {
    asm volatile("ldmatrix.sync.aligned.m8n8.x4.trans.shared.b16 {%0,%1,%2,%3}, [%4];"
                 : "=r"(r[0]), "=r"(r[1]), "=r"(r[2]), "=r"(r[3]) : "r"(addr));
}
__device__ __forceinline__ void mma_f16(float* d, const unsigned* a, const unsigned* b) {
    asm volatile(
        "mma.sync.aligned.m16n8k16.row.col.f32.f16.f16.f32 "
        "{%0,%1,%2,%3},{%4,%5,%6,%7},{%8,%9},{%0,%1,%2,%3};"
        : "+f"(d[0]), "+f"(d[1]), "+f"(d[2]), "+f"(d[3])
        : "r"(a[0]), "r"(a[1]), "r"(a[2]), "r"(a[3]),
          "r"(b[0]), "r"(b[1]));
}
__device__ __forceinline__ void red_add_v2(float* dst, float v0, float v1) {
    asm volatile("red.global.add.v2.f32 [%0], {%1, %2};"
                 :: "l"(dst), "f"(v0), "f"(v1) : "memory");
}

// ================= routing: per-token with duplicate-expert merge =======
__global__ void route_kernel(const float* __restrict__ rw,
                             const int*   __restrict__ sel) {
    __shared__ int sc[E_NUM];
    int tid = threadIdx.x;
    if (tid < E_NUM) sc[tid] = 0;
    __syncthreads();
    for (int t = tid; t < T_TOK; t += blockDim.x) {
        int   e0 = sel[2 * t],     e1 = sel[2 * t + 1];
        float r0 = rw [2 * t],     r1 = rw [2 * t + 1];
        if (e0 == e1) {
            int slot = atomicAdd(&sc[e0], 1);
            g_tok [e0 * MAXP + slot] = t;
            g_gate[e0 * MAXP + slot] = r0 + r1;
        } else {
            int s0 = atomicAdd(&sc[e0], 1);
            g_tok [e0 * MAXP + s0] = t;
            g_gate[e0 * MAXP + s0] = r0;
            int s1 = atomicAdd(&sc[e1], 1);
            g_tok [e1 * MAXP + s1] = t;
            g_gate[e1 * MAXP + s1] = r1;
        }
    }
    __syncthreads();
    if (tid == 0) {
        int off = 0;
        for (int e = 0; e < E_NUM; e++) {
            g_count[e]  = sc[e];
            g_offset[e] = off;
            off += sc[e];
        }
    }
}

// ================= x -> fp16 (token-major, no routing dep) =============
__global__ void convert_x_kernel(const float* __restrict__ x) {
    int i = blockIdx.x * blockDim.x + threadIdx.x;   // float4 index
    float4 v = ((const float4*)x)[i];
    __half2 h0 = __floats2half2_rn(v.x, v.y);
    __half2 h1 = __floats2half2_rn(v.z, v.w);
    ((uint2*)g_xh)[i] = make_uint2(*(uint32_t*)&h0, *(uint32_t*)&h1);
}

// ================= weight convert -> fp16 =================
__global__ void convert_kernel(const float* __restrict__ src,
                               __half* __restrict__ dst, int n4) {
    int i = blockIdx.x * blockDim.x + threadIdx.x;
    const int stride = gridDim.x * blockDim.x;
    for (; i < n4; i += stride) {
        float4 v = ((const float4*)src)[i];
        __half2 h0 = __floats2half2_rn(v.x, v.y);
        __half2 h1 = __floats2half2_rn(v.z, v.w);
        ((uint2*)dst)[i] = make_uint2(*(uint32_t*)&h0, *(uint32_t*)&h1);
    }
}

// ================= persistent grouped GEMM: work-stealing tiles =========
// IS_FC:  A rows gathered on the fly from token-major g_xh via g_tok.
// !IS_FC: A rows from compacted g_h; scatter via red.global.add.v2.f32.
template <bool IS_FC>
__global__ __launch_bounds__(256, 2)
void moe_gemm(const __half* __restrict__ wsrc, float* __restrict__ out) {
    const int KDIM = IS_FC ? H_DIM : I_DIM;
    const int NDIM = IS_FC ? I_DIM : H_DIM;
    const int NKB  = KDIM / BK;
    const int NX   = NDIM / BN;

    extern __shared__ char sm[];
    __shared__ int s_idx;
    const uint32_t smb = smem_u32(sm);

    const int tid  = threadIdx.x;
    const int warp = tid >> 5;
    const int lane = tid & 31;

    // fixed per-thread maps
    const int arow = tid >> 1;
    const int ahc  = (tid & 1) * 16;
    const int brow = tid >> 3;
    const int bhc  = (tid & 7) * 16;

    uint32_t aDst[NST], bDst[NST];
#pragma unroll
    for (int s = 0; s < NST; s++) {
        aDst[s] = smb + s * STG + arow * AROW_B + ahc * 2;
        bDst[s] = smb + s * STG + ABYTES + brow * BROW_B + bhc * 2;
    }

    const int wm = warp >> 2;
    const int wn = warp & 3;
    const int g  = lane >> 2;
    const int t  = lane & 3;
    const int lrow = lane & 15;
    const int lsel = lane >> 4;
    const uint32_t aLdBase = (wm * 64 + lrow) * AROW_B + lsel * 16;
    const uint32_t bLdBase = ABYTES + lrow * BROW_B + (wn * 32 + lsel * 8) * 2;

    for (;;) {
        if (tid == 0) s_idx = atomicAdd(&g_ctr[IS_FC ? 0 : 1], 1);
        __syncthreads();                    // broadcast + all warps done w/ prev tile
        int rem = s_idx;

        // decode flattened tile index -> (e, row0, col0), x-fastest
        int e = 0;
        for (; e < E_NUM; e++) {
            int te = ((g_count[e] + BM - 1) >> 7) * NX;
            if (rem < te) break;
            rem -= te;
        }
        if (e == E_NUM) return;
        const int cnt  = g_count[e];
        const int off  = g_offset[e];
        const int row0 = (rem / NX) * BM;
        const int col0 = (rem % NX) * BN;

        // per-tile source pointers
        int ga = row0 + arow; if (ga >= cnt) ga = cnt - 1;
        const __half* aSrc;
        if (IS_FC) {
            const int tok = g_tok[e * MAXP + ga];
            aSrc = g_xh + (size_t)tok * H_DIM + ahc;
        } else {
            aSrc = g_h + (size_t)(off + ga) * KDIM + ahc;
        }
        const __half* bSrc = wsrc + (size_t)e * H_DIM * I_DIM
                           + (size_t)brow * NDIM + col0 + bhc;

#define ISSUE(kb_, st_) do { \
    const __half* as_ = aSrc + (kb_) * BK; \
    cp16(aDst[st_], as_); cp16(aDst[st_] + 16, as_ + 8); \
    const __half* bs_ = bSrc + (size_t)(kb_) * BK * NDIM; \
    cp16(bDst[st_], bs_); cp16(bDst[st_] + 16, bs_ + 8); \
    } while (0)

        float acc[4][4][4];
#pragma unroll
        for (int mt = 0; mt < 4; mt++)
#pragma unroll
            for (int nt = 0; nt < 4; nt++)
#pragma unroll
                for (int r = 0; r < 4; r++) acc[mt][nt][r] = 0.f;

        ISSUE(0, 0); cp_commit();
        ISSUE(1, 1); cp_commit();
        ISSUE(2, 2); cp_commit();

#pragma unroll 1
        for (int kb = 0; kb < NKB; kb++) {
            cp_wait2();
            __syncthreads();
            const int st = kb & 3;
            if (kb + 3 < NKB) ISSUE(kb + 3, (kb + 3) & 3);
            cp_commit();

            const uint32_t stb = smb + st * STG;
#pragma unroll
            for (int ks = 0; ks < 2; ks++) {
                const int k0 = ks * 16;
                unsigned afr[4][4], bfr[2][4];
#pragma unroll
                for (int h = 0; h < 2; h++)
                    ldsm_x4_t(bfr[h], stb + bLdBase + k0 * BROW_B + h * 32);
#pragma unroll
                for (int mt = 0; mt < 4; mt++)
                    ldsm_x4(afr[mt], stb + aLdBase + mt * 16 * AROW_B + k0 * 2);
#pragma unroll
                for (int mt = 0; mt < 4; mt++) {
#pragma unroll
                    for (int nt = 0; nt < 4; nt++)
                        mma_f16(acc[mt][nt], afr[mt], &bfr[nt >> 1][(nt & 1) * 2]);
                }
            }
        }
#undef ISSUE

        // ---- epilogue ----
#pragma unroll
        for (int mt = 0; mt < 4; mt++) {
            const int l0 = wm * 64 + mt * 16 + g;
            const int l1 = l0 + 8;
            const int lr0 = row0 + l0;
            const int lr1 = row0 + l1;
#pragma unroll
            for (int nt = 0; nt < 4; nt++) {
                const int c = col0 + wn * 32 + nt * 8 + 2 * t;
                if (IS_FC) {
                    if (lr0 < cnt) {
                        __half2 v = __floats2half2_rn(gelu_exact(acc[mt][nt][0]),
                                                      gelu_exact(acc[mt][nt][1]));
                        *(__half2*)(g_h + (size_t)(off + lr0) * I_DIM + c) = v;
                    }
                    if (lr1 < cnt) {
                        __half2 v = __floats2half2_rn(gelu_exact(acc[mt][nt][2]),
                                                      gelu_exact(acc[mt][nt][3]));
                        *(__half2*)(g_h + (size_t)(off + lr1) * I_DIM + c) = v;
                    }
                } else {
                    if (lr0 < cnt) {
                        const float gate = g_gate[e * MAXP + lr0];
                        float* dst = out + (size_t)g_tok[e * MAXP + lr0] * H_DIM + c;
                        red_add_v2(dst, gate * acc[mt][nt][0], gate * acc[mt][nt][1]);
                    }
                    if (lr1 < cnt) {
                        const float gate = g_gate[e * MAXP + lr1];
                        float* dst = out + (size_t)g_tok[e * MAXP + lr1] * H_DIM + c;
                        red_add_v2(dst, gate * acc[mt][nt][2], gate * acc[mt][nt][3]);
                    }
                }
            }
        }
    }
}

// ================= launch (fork/join, two persistent GEMMs) =============
extern "C" void kernel_launch(void* const* d_in, const int* in_sizes, int n_in,
                              void* d_out, int out_size) {
    const float* x     = (const float*)d_in[0];
    const float* rw    = (const float*)d_in[1];
    const int*   sel   = (const int*)  d_in[2];
    const float* wfc   = (const float*)d_in[3];
    const float* wproj = (const float*)d_in[4];
    float* out = (float*)d_out;

    static bool inited = false;
    static cudaStream_t sA, sB;
    static cudaEvent_t ev0, evA, evB;
    if (!inited) {
        cudaStreamCreateWithFlags(&sA, cudaStreamNonBlocking);
        cudaStreamCreateWithFlags(&sB, cudaStreamNonBlocking);
        cudaEventCreateWithFlags(&ev0, cudaEventDisableTiming);
        cudaEventCreateWithFlags(&evA, cudaEventDisableTiming);
        cudaEventCreateWithFlags(&evB, cudaEventDisableTiming);
        cudaFuncSetAttribute(moe_gemm<true>,  cudaFuncAttributeMaxDynamicSharedMemorySize, SMEM_SZ);
        cudaFuncSetAttribute(moe_gemm<false>, cudaFuncAttributeMaxDynamicSharedMemorySize, SMEM_SZ);
        inited = true;
    }

    __half* wfcH;  cudaGetSymbolAddress((void**)&wfcH, g_wfc_h);
    __half* wprH;  cudaGetSymbolAddress((void**)&wprH, g_wproj_h);
    int* ctr;      cudaGetSymbolAddress((void**)&ctr,  g_ctr);

    const int n4 = E_NUM * H_DIM * I_DIM / 4;

    // fork side streams off the main (capture) stream
    cudaEventRecord(ev0, 0);
    cudaStreamWaitEvent(sA, ev0, 0);
    cudaStreamWaitEvent(sB, ev0, 0);

    // sA: convert wfc (gates fc GEMM)
    convert_kernel<<<1184, 256, 0, sA>>>(wfc, wfcH, n4);
    cudaEventRecord(evA, sA);

    // sB: convert wproj + zero output (gates proj GEMM)
    convert_kernel<<<1184, 256, 0, sB>>>(wproj, wprH, n4);
    cudaMemsetAsync(out, 0, (size_t)T_TOK * H_DIM * sizeof(float), sB);
    cudaEventRecord(evB, sB);

    // main: reset tile counters + convert x + routing
    cudaMemsetAsync(ctr, 0, 2 * sizeof(int));
    convert_x_kernel<<<T_TOK * H_DIM / 4 / 256, 256>>>(x);
    route_kernel<<<1, 512>>>(rw, sel);

    // join: fc needs wfcH + xh + routing tables
    cudaStreamWaitEvent(0, evA, 0);
    moe_gemm<true><<<PERSIST_CTAS, 256, SMEM_SZ>>>(wfcH, out);

    cudaStreamWaitEvent(0, evB, 0);
    moe_gemm<false><<<PERSIST_CTAS, 256, SMEM_SZ>>>(wprH, out);
}